// round 13
// baseline (speedup 1.0000x reference)
#include <cuda_runtime.h>
#include <cstdint>

#define NB 16384
#define NT 1024
#define HH 64
#define TPB 64                // 2 warps; 4 elements per block
#define GRID (NB / 4)         // 4096 blocks; 7/SM resident -> 3.954 waves

#define L2E2 2.8853900817779268f   // 2*log2(e), folded into W1/b1/W2/b2
// hb index: 16B gap between k-halves so kl=0/kl=1 LDS.128 hit disjoint banks
#define HIDX(k) ((k) + ((((k) >> 5)) << 2))

typedef unsigned long long u64;

static __device__ __forceinline__ u64 fma2(u64 a, u64 b, u64 c) {
    u64 d;
    asm("fma.rn.f32x2 %0, %1, %2, %3;" : "=l"(d) : "l"(a), "l"(b), "l"(c));
    return d;
}
static __device__ __forceinline__ u64 add2(u64 a, u64 b) {
    u64 d;
    asm("add.rn.f32x2 %0, %1, %2;" : "=l"(d) : "l"(a), "l"(b));
    return d;
}
static __device__ __forceinline__ u64 pk(float a, float b) {
    u64 d;
    asm("mov.b64 %0, {%1, %2};" : "=l"(d) : "f"(a), "f"(b));
    return d;
}
static __device__ __forceinline__ u64 dup2(float a) {
    u64 d;
    asm("mov.b64 %0, {%1, %1};" : "=l"(d) : "f"(a));
    return d;
}
static __device__ __forceinline__ void upk(u64 v, float& a, float& b) {
    asm("mov.b64 {%0, %1}, %2;" : "=f"(a), "=f"(b) : "l"(v));
}
static __device__ __forceinline__ u64 shfl_xor64(u64 v, int m) {
    uint32_t lo = (uint32_t)v, hi = (uint32_t)(v >> 32);
    lo = __shfl_xor_sync(0xffffffffu, lo, m);
    hi = __shfl_xor_sync(0xffffffffu, hi, m);
    return ((u64)hi << 32) | lo;
}
// tanh with prescaled arg a = 2*log2(e)*x: tanh(x) = 1 - 2/(2^a + 1).
// Validated at rel_err ~3e-7 over 1023 steps (rounds 1-12).
static __device__ __forceinline__ float tanh_pre(float a) {
    float e, r;
    asm("ex2.approx.f32 %0, %1;" : "=f"(e) : "f"(a));
    asm("rcp.approx.f32 %0, %1;" : "=f"(r) : "f"(e + 1.0f));
    return fmaf(-2.0f, r, 1.0f);
}

__device__ __constant__ float cA[5][5] = {
    {(float)(1.0 / 5.0), 0.f, 0.f, 0.f, 0.f},
    {(float)(3.0 / 40.0), (float)(9.0 / 40.0), 0.f, 0.f, 0.f},
    {(float)(44.0 / 45.0), (float)(-56.0 / 15.0), (float)(32.0 / 9.0), 0.f, 0.f},
    {(float)(19372.0 / 6561.0), (float)(-25360.0 / 2187.0),
     (float)(64448.0 / 6561.0), (float)(-212.0 / 729.0), 0.f},
    {(float)(9017.0 / 3168.0), (float)(-355.0 / 33.0),
     (float)(46732.0 / 5247.0), (float)(49.0 / 176.0),
     (float)(-5103.0 / 18656.0)},
};

__global__ void __launch_bounds__(TPB, 7)
ode_kernel(const float* __restrict__ y0, const float* __restrict__ ts,
           const float* __restrict__ W1, const float* __restrict__ b1,
           const float* __restrict__ W2, const float* __restrict__ b2,
           const float* __restrict__ W3, const float* __restrict__ b3,
           float* __restrict__ out) {
    __shared__ __align__(16) float hb[4][72];   // [m][HIDX(k)] activations
    __shared__ __align__(16) float sW1x[HH], sW1y[HH], sB1[HH];  // * L2E2
    __shared__ float2 fxy[6][2][4];             // [st][w][m] warp f-partials
    __shared__ float dts[NT];

    const int tid = threadIdx.x;
    for (int i = tid; i < NT - 1; i += TPB) dts[i] = ts[i + 1] - ts[i];
    for (int i = tid; i < HH; i += TPB) {
        sW1x[i] = W1[2 * i] * L2E2;
        sW1y[i] = W1[2 * i + 1] * L2E2;
        sB1[i] = b1[i] * L2E2;
    }

    const int lane = tid & 31;
    const int w = tid >> 5;          // warp's j-half: j in [32w, 32w+32)
    const int jl = lane & 15;        // j-pair lane: j0 = 32w + 2jl
    const int kl = lane >> 4;        // k-half within warp: k in [32kl, +32)
    const int j0 = 32 * w + 2 * jl;
    const int m1 = tid & 3;          // this thread's state element
    const int kc = tid >> 2;         // layer-1 unit quad: 4kc..4kc+3
    const int e0 = blockIdx.x * 4;

    // ---- W2 block into registers: 2 j x 16 k-pairs (k-parity packed) ----
    u64 w2r[2][16];
#pragma unroll
    for (int jp = 0; jp < 2; jp++) {
        const float4* row = (const float4*)(W2 + (j0 + jp) * HH + 32 * kl);
#pragma unroll
        for (int q = 0; q < 8; q++) {
            const float4 v = row[q];
            w2r[jp][2 * q]     = pk(v.x * L2E2, v.y * L2E2);
            w2r[jp][2 * q + 1] = pk(v.z * L2E2, v.w * L2E2);
        }
    }
    // ---- phase-D constants for this lane's 2 j's ----
    float b2r[2];
    u64 w3r[2];
#pragma unroll
    for (int jp = 0; jp < 2; jp++) {
        b2r[jp] = b2[j0 + jp] * L2E2;
        w3r[jp] = pk(W3[j0 + jp], W3[HH + j0 + jp]);
    }
    const float b3x = b3[0], b3y = b3[1];

    const float2 yv = ((const float2*)y0)[e0 + m1];
    float yx = yv.x, yy = yv.y;
    float2* o2 = (float2*)out;
    if (tid < 4) o2[e0 + m1] = yv;   // SaveAt includes the initial state
    __syncthreads();                 // smem tables ready

    const float B1 = (float)(35.0 / 384.0);
    const float B3 = (float)(500.0 / 1113.0);
    const float B4 = (float)(125.0 / 192.0);
    const float B5 = (float)(-2187.0 / 6784.0);
    const float B6 = (float)(11.0 / 84.0);

    const int hoff = 36 * kl;        // HIDX(32*kl)

    for (int t = 0; t < NT - 1; t++) {
        const float dtv = dts[t];
        float kx6[6], ky6[6];

#pragma unroll 1
        for (int st = 0; st < 6; st++) {
            // ---- stage input for element m1 ----
            float sx, sy;
            if (st == 0) {
                sx = yx; sy = yy;
            } else {
                float ax = 0.f, ay = 0.f;
                for (int i = 0; i < st; i++) {
                    const float a = cA[st - 1][i];
                    ax = fmaf(a, kx6[i], ax);
                    ay = fmaf(a, ky6[i], ay);
                }
                sx = fmaf(dtv, ax, yx);
                sy = fmaf(dtv, ay, yy);
            }

            // ---- layer 1: 4 units (k = 4kc..4kc+3) for element m1 ----
            {
                const float4 wx = *(const float4*)&sW1x[4 * kc];
                const float4 wy = *(const float4*)&sW1y[4 * kc];
                const float4 bb = *(const float4*)&sB1[4 * kc];
                float4 hv;
                hv.x = tanh_pre(fmaf(sx, wx.x, fmaf(sy, wy.x, bb.x)));
                hv.y = tanh_pre(fmaf(sx, wx.y, fmaf(sy, wy.y, bb.y)));
                hv.z = tanh_pre(fmaf(sx, wx.z, fmaf(sy, wy.z, bb.z)));
                hv.w = tanh_pre(fmaf(sx, wx.w, fmaf(sy, wy.w, bb.w)));
                *(float4*)&hb[m1][HIDX(4 * kc)] = hv;
            }
            __syncthreads();   // hb complete (cross-warp k coverage)

            // ---- layer 2: reg weights, natural-pair h, NO duplication ----
            u64 acc[4][2];
#pragma unroll
            for (int m = 0; m < 4; m++) { acc[m][0] = 0ull; acc[m][1] = 0ull; }

#pragma unroll
            for (int q = 0; q < 8; q++) {
                const u64 wa0 = w2r[0][2 * q], wa1 = w2r[0][2 * q + 1];
                const u64 wb0 = w2r[1][2 * q], wb1 = w2r[1][2 * q + 1];
#pragma unroll
                for (int m = 0; m < 4; m++) {
                    const float4 hvq = *(const float4*)&hb[m][hoff + 4 * q];
                    const u64 pA = ((const u64*)&hvq)[0];  // (h_even, h_odd)
                    const u64 pB = ((const u64*)&hvq)[1];
                    acc[m][0] = fma2(pA, wa0, acc[m][0]);
                    acc[m][1] = fma2(pA, wb0, acc[m][1]);
                    acc[m][0] = fma2(pB, wa1, acc[m][0]);
                    acc[m][1] = fma2(pB, wb1, acc[m][1]);
                }
            }

            // ---- reduce over the 2 kl lanes (split-butterfly, m-halved) ----
            u64 red[2][2];   // [r][jp], m = 2*kl + r
#pragma unroll
            for (int r = 0; r < 2; r++)
#pragma unroll
                for (int jp = 0; jp < 2; jp++) {
                    const u64 gv = kl ? acc[r][jp] : acc[2 + r][jp];
                    const u64 kv = kl ? acc[2 + r][jp] : acc[r][jp];
                    red[r][jp] = add2(kv, shfl_xor64(gv, 16));
                }

            // ---- phase D: hi+lo merge, bias, tanh, layer 3 ----
            u64 accP[2];
#pragma unroll
            for (int r = 0; r < 2; r++) {
                float l0, h0, l1, h1;
                upk(red[r][0], l0, h0);
                upk(red[r][1], l1, h1);
                const float g0 = tanh_pre(l0 + h0 + b2r[0]);
                const float g1 = tanh_pre(l1 + h1 + b2r[1]);
                accP[r] = fma2(dup2(g0), w3r[0], fma2(dup2(g1), w3r[1], 0ull));
            }

            // ---- reduce over 16 jl lanes (first round splits m) ----
            {
                const int p = jl & 1;
                const u64 gv = p ? accP[0] : accP[1];
                const u64 kv = p ? accP[1] : accP[0];
                u64 s = add2(kv, shfl_xor64(gv, 1));   // m = 2*kl + p
                s = add2(s, shfl_xor64(s, 2));
                s = add2(s, shfl_xor64(s, 4));
                s = add2(s, shfl_xor64(s, 8));
                if (jl < 2) {
                    float fx, fy;
                    upk(s, fx, fy);
                    fxy[st][w][2 * kl + jl] = make_float2(fx, fy);
                }
            }
            __syncthreads();   // fxy complete; WAR cover for hb next stage

            const float2 fa = fxy[st][0][m1];
            const float2 fb = fxy[st][1][m1];
            kx6[st] = fa.x + fb.x + b3x;
            ky6[st] = fa.y + fb.y + b3y;
        }

        // ---- combine and advance ----
        float ax = B1 * kx6[0], ay = B1 * ky6[0];
        ax = fmaf(B3, kx6[2], ax); ay = fmaf(B3, ky6[2], ay);
        ax = fmaf(B4, kx6[3], ax); ay = fmaf(B4, ky6[3], ay);
        ax = fmaf(B5, kx6[4], ax); ay = fmaf(B5, ky6[4], ay);
        ax = fmaf(B6, kx6[5], ax); ay = fmaf(B6, ky6[5], ay);
        yx = fmaf(dtv, ax, yx);
        yy = fmaf(dtv, ay, yy);
        if (tid < 4)
            o2[(size_t)(t + 1) * NB + e0 + m1] = make_float2(yx, yy);
    }
}

extern "C" void kernel_launch(void* const* d_in, const int* in_sizes, int n_in,
                              void* d_out, int out_size) {
    const float* y0 = (const float*)d_in[0];
    const float* ts = (const float*)d_in[1];
    const float* W1 = (const float*)d_in[2];
    const float* b1 = (const float*)d_in[3];
    const float* W2 = (const float*)d_in[4];
    const float* b2 = (const float*)d_in[5];
    const float* W3 = (const float*)d_in[6];
    const float* b3 = (const float*)d_in[7];
    ode_kernel<<<GRID, TPB>>>(y0, ts, W1, b1, W2, b2, W3, b3, (float*)d_out);
}

// round 14
// speedup vs baseline: 3.5033x; 3.5033x over previous
#include <cuda_runtime.h>
#include <cstdint>

#define NB 16384
#define NT 1024
#define HH 64
#define TPB 64                 // warp-pair: 16 elements; j split 32/32
#define GRID (NB / 16)         // 1024 blocks (single wave at 7 blocks/SM)

#define L2E2 2.8853900817779268f   // 2*log2(e), folded into W1/b1/W2/b2

typedef unsigned long long u64;
typedef uint32_t u32;

static __device__ __forceinline__ u64 fma2(u64 a, u64 b, u64 c) {
    u64 d;
    asm("fma.rn.f32x2 %0, %1, %2, %3;" : "=l"(d) : "l"(a), "l"(b), "l"(c));
    return d;
}
static __device__ __forceinline__ u64 add2(u64 a, u64 b) {
    u64 d;
    asm("add.rn.f32x2 %0, %1, %2;" : "=l"(d) : "l"(a), "l"(b));
    return d;
}
static __device__ __forceinline__ u64 pk(float a, float b) {
    u64 d;
    asm("mov.b64 %0, {%1, %2};" : "=l"(d) : "f"(a), "f"(b));
    return d;
}
static __device__ __forceinline__ u64 dup2(float a) {
    u64 d;
    asm("mov.b64 %0, {%1, %1};" : "=l"(d) : "f"(a));
    return d;
}
static __device__ __forceinline__ void upk(u64 v, float& a, float& b) {
    asm("mov.b64 {%0, %1}, %2;" : "=f"(a), "=f"(b) : "l"(v));
}
static __device__ __forceinline__ u64 shfl_xor64(u64 v, int m) {
    u32 lo = (u32)v, hi = (u32)(v >> 32);
    lo = __shfl_xor_sync(0xffffffffu, lo, m);
    hi = __shfl_xor_sync(0xffffffffu, hi, m);
    return ((u64)hi << 32) | lo;
}
// tanh with prescaled arg a = 2*log2(e)*x: tanh(x) = 1 - 2/(2^a + 1).
static __device__ __forceinline__ float tanh_pre(float a) {
    float e, r;
    asm("ex2.approx.f32 %0, %1;" : "=f"(e) : "f"(a));
    asm("rcp.approx.f32 %0, %1;" : "=f"(r) : "f"(e + 1.0f));
    return fmaf(-2.0f, r, 1.0f);
}
// pack two f32 -> bf16x2; lo half = first arg (PTX: first source -> upper).
static __device__ __forceinline__ u32 bfpack(float lo, float hi) {
    u32 d;
    asm("cvt.rn.bf16x2.f32 %0, %1, %2;" : "=r"(d) : "f"(hi), "f"(lo));
    return d;
}
// m16n8k16 row.col bf16 MMA, fp32 accumulate (plain sm_80+ HMMA).
static __device__ __forceinline__ void mma_bf16(float& d0, float& d1, float& d2,
                                                float& d3, u32 a0, u32 a1,
                                                u32 a2, u32 a3, u32 b0, u32 b1) {
    asm("mma.sync.aligned.m16n8k16.row.col.f32.bf16.bf16.f32 "
        "{%0,%1,%2,%3}, {%4,%5,%6,%7}, {%8,%9}, {%0,%1,%2,%3};"
        : "+f"(d0), "+f"(d1), "+f"(d2), "+f"(d3)
        : "r"(a0), "r"(a1), "r"(a2), "r"(a3), "r"(b0), "r"(b1));
}

__device__ __constant__ float2 cA2[5][5] = {
    {{1.f/5, 1.f/5}, {0,0}, {0,0}, {0,0}, {0,0}},
    {{3.f/40, 3.f/40}, {9.f/40, 9.f/40}, {0,0}, {0,0}, {0,0}},
    {{44.f/45, 44.f/45}, {-56.f/15, -56.f/15}, {32.f/9, 32.f/9}, {0,0}, {0,0}},
    {{(float)(19372.0/6561.0), (float)(19372.0/6561.0)},
     {(float)(-25360.0/2187.0), (float)(-25360.0/2187.0)},
     {(float)(64448.0/6561.0), (float)(64448.0/6561.0)},
     {(float)(-212.0/729.0), (float)(-212.0/729.0)}, {0,0}},
    {{(float)(9017.0/3168.0), (float)(9017.0/3168.0)},
     {(float)(-355.0/33.0), (float)(-355.0/33.0)},
     {(float)(46732.0/5247.0), (float)(46732.0/5247.0)},
     {(float)(49.0/176.0), (float)(49.0/176.0)},
     {(float)(-5103.0/18656.0), (float)(-5103.0/18656.0)}},
};
__device__ __constant__ float2 cB2[5] = {
    {(float)(35.0/384.0), (float)(35.0/384.0)},
    {(float)(500.0/1113.0), (float)(500.0/1113.0)},
    {(float)(125.0/192.0), (float)(125.0/192.0)},
    {(float)(-2187.0/6784.0), (float)(-2187.0/6784.0)},
    {(float)(11.0/84.0), (float)(11.0/84.0)},
};

__global__ void __launch_bounds__(TPB, 7)
ode_kernel(const float* __restrict__ y0, const float* __restrict__ ts,
           const float* __restrict__ W1, const float* __restrict__ b1,
           const float* __restrict__ W2, const float* __restrict__ b2,
           const float* __restrict__ W3, const float* __restrict__ b3,
           float* __restrict__ out) {
    __shared__ u32 tabblo[16][64][2];   // W2 lo-residual B fragments (8 KB)
    __shared__ float tw1x[8][64], tw1y[8][64], tb1[8][64];  // per-lane L1 (6 KB)
    __shared__ u64 tw3[8][64];          // per-lane W3 pairs (4 KB)
    __shared__ u64 tb2[4][64];          // per-lane b2 init pairs (2 KB)
    __shared__ u32 afp[4 * 8 * 32];     // A-fragment exchange (4 KB)
    __shared__ u64 pbuf[2][16];         // cross-warp layer-3 partials
    __shared__ u64 ksm[2][6][16];       // per-warp RK stage values (1.5 KB)
    __shared__ float dts[NT];

    const int tid = threadIdx.x;
    const int w = tid >> 5, lane = tid & 31;
    const int gid = lane >> 2, tig = lane & 3;

    for (int i = tid; i < NT - 1; i += TPB) dts[i] = ts[i + 1] - ts[i];

    // ---- per-lane layer-1 table (unit set matches A-fragment cols) ----
#pragma unroll
    for (int q = 0; q < 8; q++) {
        const int ksl = q >> 2, idx = q & 3;
        const int ks = 2 * w + ksl;
        const int u = 16 * ks + 2 * tig + (idx & 1) + 8 * (idx >> 1);
        tw1x[q][tid] = W1[2 * u] * L2E2;
        tw1y[q][tid] = W1[2 * u + 1] * L2E2;
        tb1[q][tid] = b1[u] * L2E2;
    }
    // ---- per-lane W3 pairs: q = 2*nt + c -> j = 32w + 8nt + 2tig + c ----
#pragma unroll
    for (int q = 0; q < 8; q++) {
        const int j = 32 * w + 8 * (q >> 1) + 2 * tig + (q & 1);
        tw3[q][tid] = pk(W3[j], W3[HH + j]);
    }
    // ---- per-lane b2 accumulator-init pairs ----
#pragma unroll
    for (int nt = 0; nt < 4; nt++) {
        const int j0 = 32 * w + 8 * nt + 2 * tig;
        tb2[nt][tid] = pk(b2[j0] * L2E2, b2[j0 + 1] * L2E2);
    }
    // ---- B fragments: hi in registers, lo residual in smem ----
    u32 bh[4][4][2];
#pragma unroll
    for (int ks = 0; ks < 4; ks++)
#pragma unroll
        for (int nt = 0; nt < 4; nt++) {
            const int j = 32 * w + 8 * nt + gid;   // B col = n = j
#pragma unroll
            for (int r = 0; r < 2; r++) {
                const int k0 = 16 * ks + 2 * tig + 8 * r;  // B rows = k
                const float v0 = W2[j * HH + k0] * L2E2;
                const float v1 = W2[j * HH + k0 + 1] * L2E2;
                const u32 ph = bfpack(v0, v1);
                const float r0 = v0 - __uint_as_float(ph << 16);
                const float r1 = v1 - __uint_as_float(ph & 0xffff0000u);
                bh[ks][nt][r] = ph;
                tabblo[ks * 4 + nt][tid][r] = bfpack(r0, r1);
            }
        }
    __syncthreads();

    const int e0 = blockIdx.x * 16;
    u64 y_lo = ((const u64*)y0)[e0 + gid];       // element gid
    u64 y_hi = ((const u64*)y0)[e0 + gid + 8];   // element gid+8
    u64* o8 = (u64*)out;
    if (w == 0 && tig == 0) {   // SaveAt includes the initial state
        o8[e0 + gid] = y_lo;
        o8[e0 + gid + 8] = y_hi;
    }
    const u64 b3p = pk(b3[0], b3[1]);

    for (int t = 0; t < NT - 1; t++) {
        const float dtv = dts[t];
        const u64 dtp = dup2(dtv);

#pragma unroll 1
        for (int st = 0; st < 6; st++) {
            // ---- stage input (both elements; per-warp ksm copy) ----
            u64 s_lo, s_hi;
            if (st == 0) {
                s_lo = y_lo; s_hi = y_hi;
            } else {
                u64 al = 0ull, ah = 0ull;
                for (int i = 0; i < st; i++) {
                    const float2 cc = cA2[st - 1][i];
                    const u64 c = *(const u64*)&cc;
                    al = fma2(c, ksm[w][i][gid], al);
                    ah = fma2(c, ksm[w][i][gid + 8], ah);
                }
                s_lo = fma2(dtp, al, y_lo);
                s_hi = fma2(dtp, ah, y_hi);
            }
            float sxl, syl, sxh, syh;
            upk(s_lo, sxl, syl);
            upk(s_hi, sxh, syh);

            // ---- layer 1 for this warp's 2 k-steps -> packed A frags ----
#pragma unroll
            for (int ksl = 0; ksl < 2; ksl++) {
                float hl[4], hh[4];
#pragma unroll
                for (int idx = 0; idx < 4; idx++) {
                    const int q = 4 * ksl + idx;
                    const float wx = tw1x[q][tid];
                    const float wy = tw1y[q][tid];
                    const float bb = tb1[q][tid];
                    hl[idx] = tanh_pre(fmaf(sxl, wx, fmaf(syl, wy, bb)));
                    hh[idx] = tanh_pre(fmaf(sxh, wx, fmaf(syh, wy, bb)));
                }
                // hi fragments (a0: row gid cols c0c1; a1: row gid+8; a2/a3: +8 cols)
                const u32 p0 = bfpack(hl[0], hl[1]);
                const u32 p1 = bfpack(hh[0], hh[1]);
                const u32 p2 = bfpack(hl[2], hl[3]);
                const u32 p3 = bfpack(hh[2], hh[3]);
                // lo residuals (bf16 -> f32 is a 16-bit shift)
                const u32 q0 = bfpack(hl[0] - __uint_as_float(p0 << 16),
                                      hl[1] - __uint_as_float(p0 & 0xffff0000u));
                const u32 q1 = bfpack(hh[0] - __uint_as_float(p1 << 16),
                                      hh[1] - __uint_as_float(p1 & 0xffff0000u));
                const u32 q2 = bfpack(hl[2] - __uint_as_float(p2 << 16),
                                      hl[3] - __uint_as_float(p2 & 0xffff0000u));
                const u32 q3 = bfpack(hh[2] - __uint_as_float(p3 << 16),
                                      hh[3] - __uint_as_float(p3 & 0xffff0000u));
                const int base = ((2 * w + ksl) * 8) * 32 + lane;
                afp[base] = p0;
                afp[base + 32] = p1;
                afp[base + 64] = p2;
                afp[base + 96] = p3;
                afp[base + 128] = q0;
                afp[base + 160] = q1;
                afp[base + 192] = q2;
                afp[base + 224] = q3;
            }
            __syncthreads();   // all 4 k-steps of A available

            u32 ahi[4][4], alo[4][4];
#pragma unroll
            for (int ks = 0; ks < 4; ks++)
#pragma unroll
                for (int r = 0; r < 4; r++) {
                    ahi[ks][r] = afp[(ks * 8 + r) * 32 + lane];
                    alo[ks][r] = afp[(ks * 8 + 4 + r) * 32 + lane];
                }

            // ---- layer 2 MMAs + fused epilogue (this warp's 32 j) ----
            u64 accP_lo = 0ull, accP_hi = 0ull;
#pragma unroll
            for (int nt = 0; nt < 4; nt++) {
                float d0, d1, d2, d3;
                {
                    float blo, bhi2;
                    upk(tb2[nt][tid], blo, bhi2);
                    d0 = blo; d1 = bhi2; d2 = blo; d3 = bhi2;
                }
#pragma unroll
                for (int ks = 0; ks < 4; ks++) {
                    const u64 blp = *(const u64*)&tabblo[ks * 4 + nt][tid][0];
                    const u32 bl0 = (u32)blp, bl1 = (u32)(blp >> 32);
                    mma_bf16(d0, d1, d2, d3, ahi[ks][0], ahi[ks][1], ahi[ks][2],
                             ahi[ks][3], bh[ks][nt][0], bh[ks][nt][1]);
                    mma_bf16(d0, d1, d2, d3, ahi[ks][0], ahi[ks][1], ahi[ks][2],
                             ahi[ks][3], bl0, bl1);
                    mma_bf16(d0, d1, d2, d3, alo[ks][0], alo[ks][1], alo[ks][2],
                             alo[ks][3], bh[ks][nt][0], bh[ks][nt][1]);
                }
                const float g0 = tanh_pre(d0);
                const float g1 = tanh_pre(d1);
                const float g2 = tanh_pre(d2);
                const float g3 = tanh_pre(d3);
                const u64 w3a = tw3[2 * nt][tid];
                const u64 w3b = tw3[2 * nt + 1][tid];
                accP_lo = fma2(dup2(g0), w3a, accP_lo);
                accP_lo = fma2(dup2(g1), w3b, accP_lo);
                accP_hi = fma2(dup2(g2), w3a, accP_hi);
                accP_hi = fma2(dup2(g3), w3b, accP_hi);
            }

            // ---- reduce over the 4 tig lanes of each element row ----
            accP_lo = add2(accP_lo, shfl_xor64(accP_lo, 1));
            accP_lo = add2(accP_lo, shfl_xor64(accP_lo, 2));
            accP_hi = add2(accP_hi, shfl_xor64(accP_hi, 1));
            accP_hi = add2(accP_hi, shfl_xor64(accP_hi, 2));
            if (tig == 0) {
                pbuf[w][gid] = accP_lo;
                pbuf[w][gid + 8] = accP_hi;
            }
            __syncthreads();   // partials ready; also WAR cover for afp

            const u64 k_lo = add2(add2(pbuf[0][gid], pbuf[1][gid]), b3p);
            const u64 k_hi = add2(add2(pbuf[0][gid + 8], pbuf[1][gid + 8]), b3p);
            ksm[w][st][gid] = k_lo;        // per-warp copy: no cross-warp race
            ksm[w][st][gid + 8] = k_hi;    // (4 tig lanes write same value)
        }

        // ---- combine and advance ----
        {
            u64 cl = 0ull, ch = 0ull;
            const int sidx[5] = {0, 2, 3, 4, 5};
#pragma unroll
            for (int i = 0; i < 5; i++) {
                const float2 cc = cB2[i];
                const u64 c = *(const u64*)&cc;
                cl = fma2(c, ksm[w][sidx[i]][gid], cl);
                ch = fma2(c, ksm[w][sidx[i]][gid + 8], ch);
            }
            y_lo = fma2(dtp, cl, y_lo);
            y_hi = fma2(dtp, ch, y_hi);
        }
        if (w == 0 && tig == 0) {
            o8[(size_t)(t + 1) * NB + e0 + gid] = y_lo;
            o8[(size_t)(t + 1) * NB + e0 + gid + 8] = y_hi;
        }
    }
}

extern "C" void kernel_launch(void* const* d_in, const int* in_sizes, int n_in,
                              void* d_out, int out_size) {
    const float* y0 = (const float*)d_in[0];
    const float* ts = (const float*)d_in[1];
    const float* W1 = (const float*)d_in[2];
    const float* b1 = (const float*)d_in[3];
    const float* W2 = (const float*)d_in[4];
    const float* b2 = (const float*)d_in[5];
    const float* W3 = (const float*)d_in[6];
    const float* b3 = (const float*)d_in[7];
    ode_kernel<<<GRID, TPB>>>(y0, ts, W1, b1, W2, b2, W3, b3, (float*)d_out);
}

// round 15
// speedup vs baseline: 3.7058x; 1.0578x over previous
#include <cuda_runtime.h>
#include <cstdint>

#define NB 16384
#define NT 1024
#define HH 64
#define TPB 64                 // warp-pair: 16 elements; j split 32/32
#define GRID (NB / 16)         // 1024 blocks (single wave at 7 blocks/SM)

#define L2E2 2.8853900817779268f   // 2*log2(e), folded into W1/b1/W2/b2

typedef unsigned long long u64;
typedef uint32_t u32;

static __device__ __forceinline__ u64 fma2(u64 a, u64 b, u64 c) {
    u64 d;
    asm("fma.rn.f32x2 %0, %1, %2, %3;" : "=l"(d) : "l"(a), "l"(b), "l"(c));
    return d;
}
static __device__ __forceinline__ u64 add2(u64 a, u64 b) {
    u64 d;
    asm("add.rn.f32x2 %0, %1, %2;" : "=l"(d) : "l"(a), "l"(b));
    return d;
}
static __device__ __forceinline__ u64 pk(float a, float b) {
    u64 d;
    asm("mov.b64 %0, {%1, %2};" : "=l"(d) : "f"(a), "f"(b));
    return d;
}
static __device__ __forceinline__ u64 dup2(float a) {
    u64 d;
    asm("mov.b64 %0, {%1, %1};" : "=l"(d) : "f"(a));
    return d;
}
static __device__ __forceinline__ void upk(u64 v, float& a, float& b) {
    asm("mov.b64 {%0, %1}, %2;" : "=f"(a), "=f"(b) : "l"(v));
}
static __device__ __forceinline__ u64 shfl_xor64(u64 v, int m) {
    u32 lo = (u32)v, hi = (u32)(v >> 32);
    lo = __shfl_xor_sync(0xffffffffu, lo, m);
    hi = __shfl_xor_sync(0xffffffffu, hi, m);
    return ((u64)hi << 32) | lo;
}
// tanh with prescaled arg a = 2*log2(e)*x: tanh(x) = 1 - 2/(2^a + 1).
static __device__ __forceinline__ float tanh_pre(float a) {
    float e, r;
    asm("ex2.approx.f32 %0, %1;" : "=f"(e) : "f"(a));
    asm("rcp.approx.f32 %0, %1;" : "=f"(r) : "f"(e + 1.0f));
    return fmaf(-2.0f, r, 1.0f);
}
// pack two f32 -> bf16x2; lo half = first arg (PTX: first source -> upper).
static __device__ __forceinline__ u32 bfpack(float lo, float hi) {
    u32 d;
    asm("cvt.rn.bf16x2.f32 %0, %1, %2;" : "=r"(d) : "f"(hi), "f"(lo));
    return d;
}
// m16n8k16 row.col bf16 MMA, fp32 accumulate (plain sm_80+ HMMA).
static __device__ __forceinline__ void mma_bf16(float& d0, float& d1, float& d2,
                                                float& d3, u32 a0, u32 a1,
                                                u32 a2, u32 a3, u32 b0, u32 b1) {
    asm("mma.sync.aligned.m16n8k16.row.col.f32.bf16.bf16.f32 "
        "{%0,%1,%2,%3}, {%4,%5,%6,%7}, {%8,%9}, {%0,%1,%2,%3};"
        : "+f"(d0), "+f"(d1), "+f"(d2), "+f"(d3)
        : "r"(a0), "r"(a1), "r"(a2), "r"(a3), "r"(b0), "r"(b1));
}

__device__ __constant__ float2 cA2[5][5] = {
    {{1.f/5, 1.f/5}, {0,0}, {0,0}, {0,0}, {0,0}},
    {{3.f/40, 3.f/40}, {9.f/40, 9.f/40}, {0,0}, {0,0}, {0,0}},
    {{44.f/45, 44.f/45}, {-56.f/15, -56.f/15}, {32.f/9, 32.f/9}, {0,0}, {0,0}},
    {{(float)(19372.0/6561.0), (float)(19372.0/6561.0)},
     {(float)(-25360.0/2187.0), (float)(-25360.0/2187.0)},
     {(float)(64448.0/6561.0), (float)(64448.0/6561.0)},
     {(float)(-212.0/729.0), (float)(-212.0/729.0)}, {0,0}},
    {{(float)(9017.0/3168.0), (float)(9017.0/3168.0)},
     {(float)(-355.0/33.0), (float)(-355.0/33.0)},
     {(float)(46732.0/5247.0), (float)(46732.0/5247.0)},
     {(float)(49.0/176.0), (float)(49.0/176.0)},
     {(float)(-5103.0/18656.0), (float)(-5103.0/18656.0)}},
};
// Per-stage output weights (b2 of Dopri5 is 0 at stage index 1).
__device__ __constant__ float2 cB6[6] = {
    {(float)(35.0/384.0), (float)(35.0/384.0)},
    {0.f, 0.f},
    {(float)(500.0/1113.0), (float)(500.0/1113.0)},
    {(float)(125.0/192.0), (float)(125.0/192.0)},
    {(float)(-2187.0/6784.0), (float)(-2187.0/6784.0)},
    {(float)(11.0/84.0), (float)(11.0/84.0)},
};

__global__ void __launch_bounds__(TPB, 7)
ode_kernel(const float* __restrict__ y0, const float* __restrict__ ts,
           const float* __restrict__ W1, const float* __restrict__ b1,
           const float* __restrict__ W2, const float* __restrict__ b2,
           const float* __restrict__ W3, const float* __restrict__ b3,
           float* __restrict__ out) {
    __shared__ u32 tabblo[16][64][2];                  // W2 lo B frags (8 KB)
    __shared__ __align__(16) float tw1pk[8][64][4];    // (wx,wy,b,0) (8 KB)
    __shared__ __align__(16) u64 tw3pk[4][64][2];      // W3 pairs (4 KB)
    __shared__ u64 tb2[4][64];                          // b2 init pairs (2 KB)
    __shared__ __align__(16) u32 afp[4][2][32][4];      // A-frag exch (4 KB)
    __shared__ u64 pbuf[2][16];                         // layer-3 partials
    __shared__ u64 ksm[2][6][16];                       // per-warp RK k's

    const int tid = threadIdx.x;
    const int w = tid >> 5, lane = tid & 31;
    const int gid = lane >> 2, tig = lane & 3;

    // ---- per-lane layer-1 table (unit set matches A-fragment cols) ----
#pragma unroll
    for (int q = 0; q < 8; q++) {
        const int ksl = q >> 2, idx = q & 3;
        const int ks = 2 * w + ksl;
        const int u = 16 * ks + 2 * tig + (idx & 1) + 8 * (idx >> 1);
        tw1pk[q][tid][0] = W1[2 * u] * L2E2;
        tw1pk[q][tid][1] = W1[2 * u + 1] * L2E2;
        tw1pk[q][tid][2] = b1[u] * L2E2;
        tw1pk[q][tid][3] = 0.f;
    }
    // ---- per-lane W3 pairs: tw3pk[nt][tid][c] for j = 32w+8nt+2tig+c ----
#pragma unroll
    for (int q = 0; q < 8; q++) {
        const int j = 32 * w + 8 * (q >> 1) + 2 * tig + (q & 1);
        tw3pk[q >> 1][tid][q & 1] = pk(W3[j], W3[HH + j]);
    }
    // ---- per-lane b2 accumulator-init pairs ----
#pragma unroll
    for (int nt = 0; nt < 4; nt++) {
        const int j0 = 32 * w + 8 * nt + 2 * tig;
        tb2[nt][tid] = pk(b2[j0] * L2E2, b2[j0 + 1] * L2E2);
    }
    // ---- B fragments: hi in registers, lo residual in smem ----
    u32 bh[4][4][2];
#pragma unroll
    for (int ks = 0; ks < 4; ks++)
#pragma unroll
        for (int nt = 0; nt < 4; nt++) {
            const int j = 32 * w + 8 * nt + gid;   // B col = n = j
#pragma unroll
            for (int r = 0; r < 2; r++) {
                const int k0 = 16 * ks + 2 * tig + 8 * r;  // B rows = k
                const float v0 = W2[j * HH + k0] * L2E2;
                const float v1 = W2[j * HH + k0 + 1] * L2E2;
                const u32 ph = bfpack(v0, v1);
                const float r0 = v0 - __uint_as_float(ph << 16);
                const float r1 = v1 - __uint_as_float(ph & 0xffff0000u);
                bh[ks][nt][r] = ph;
                tabblo[ks * 4 + nt][tid][r] = bfpack(r0, r1);
            }
        }
    __syncthreads();

    const int e0 = blockIdx.x * 16;
    u64 y_lo = ((const u64*)y0)[e0 + gid];       // element gid
    u64 y_hi = ((const u64*)y0)[e0 + gid + 8];   // element gid+8
    u64* o8 = (u64*)out;
    if (w == 0 && tig == 0) {   // SaveAt includes the initial state
        o8[e0 + gid] = y_lo;
        o8[e0 + gid + 8] = y_hi;
    }
    const u64 b3p = pk(b3[0], b3[1]);

    for (int t = 0; t < NT - 1; t++) {
        const float dtv = ts[t + 1] - ts[t];     // L1/L2-cached LDG
        const u64 dtp = dup2(dtv);
        u64 comb_lo = 0ull, comb_hi = 0ull;      // running B-combine

#pragma unroll 1
        for (int st = 0; st < 6; st++) {
            // ---- stage input (both elements; per-warp ksm copy) ----
            u64 s_lo, s_hi;
            if (st == 0) {
                s_lo = y_lo; s_hi = y_hi;
            } else {
                u64 al = 0ull, ah = 0ull;
                for (int i = 0; i < st; i++) {
                    const float2 cc = cA2[st - 1][i];
                    const u64 c = *(const u64*)&cc;
                    al = fma2(c, ksm[w][i][gid], al);
                    ah = fma2(c, ksm[w][i][gid + 8], ah);
                }
                s_lo = fma2(dtp, al, y_lo);
                s_hi = fma2(dtp, ah, y_hi);
            }
            float sxl, syl, sxh, syh;
            upk(s_lo, sxl, syl);
            upk(s_hi, sxh, syh);

            // ---- layer 1 for this warp's 2 k-steps -> packed A frags ----
#pragma unroll
            for (int ksl = 0; ksl < 2; ksl++) {
                float hl[4], hh[4];
#pragma unroll
                for (int idx = 0; idx < 4; idx++) {
                    const float4 wv = *(const float4*)&tw1pk[4 * ksl + idx][tid][0];
                    hl[idx] = tanh_pre(fmaf(sxl, wv.x, fmaf(syl, wv.y, wv.z)));
                    hh[idx] = tanh_pre(fmaf(sxh, wv.x, fmaf(syh, wv.y, wv.z)));
                }
                // hi fragments (a0: row gid; a1: row gid+8; a2/a3: cols +8)
                const u32 p0 = bfpack(hl[0], hl[1]);
                const u32 p1 = bfpack(hh[0], hh[1]);
                const u32 p2 = bfpack(hl[2], hl[3]);
                const u32 p3 = bfpack(hh[2], hh[3]);
                // lo residuals (bf16 -> f32 is a 16-bit shift)
                const u32 q0 = bfpack(hl[0] - __uint_as_float(p0 << 16),
                                      hl[1] - __uint_as_float(p0 & 0xffff0000u));
                const u32 q1 = bfpack(hh[0] - __uint_as_float(p1 << 16),
                                      hh[1] - __uint_as_float(p1 & 0xffff0000u));
                const u32 q2 = bfpack(hl[2] - __uint_as_float(p2 << 16),
                                      hl[3] - __uint_as_float(p2 & 0xffff0000u));
                const u32 q3 = bfpack(hh[2] - __uint_as_float(p3 << 16),
                                      hh[3] - __uint_as_float(p3 & 0xffff0000u));
                // producer lane l holds exactly consumer lane l's fragments
                *(uint4*)&afp[2 * w + ksl][0][lane][0] = make_uint4(p0, p1, p2, p3);
                *(uint4*)&afp[2 * w + ksl][1][lane][0] = make_uint4(q0, q1, q2, q3);
            }
            __syncthreads();   // all 4 k-steps of A available

            u32 ahi[4][4], alo[4][4];
#pragma unroll
            for (int ks = 0; ks < 4; ks++) {
                const uint4 hv = *(const uint4*)&afp[ks][0][lane][0];
                const uint4 lv = *(const uint4*)&afp[ks][1][lane][0];
                ahi[ks][0] = hv.x; ahi[ks][1] = hv.y;
                ahi[ks][2] = hv.z; ahi[ks][3] = hv.w;
                alo[ks][0] = lv.x; alo[ks][1] = lv.y;
                alo[ks][2] = lv.z; alo[ks][3] = lv.w;
            }

            // ---- layer 2 MMAs + fused epilogue (this warp's 32 j) ----
            u64 accP_lo = 0ull, accP_hi = 0ull;
#pragma unroll
            for (int nt = 0; nt < 4; nt++) {
                float d0, d1, d2, d3;
                {
                    float blo, bhi2;
                    upk(tb2[nt][tid], blo, bhi2);
                    d0 = blo; d1 = bhi2; d2 = blo; d3 = bhi2;
                }
#pragma unroll
                for (int ks = 0; ks < 4; ks++) {
                    const u64 blp = *(const u64*)&tabblo[ks * 4 + nt][tid][0];
                    const u32 bl0 = (u32)blp, bl1 = (u32)(blp >> 32);
                    mma_bf16(d0, d1, d2, d3, ahi[ks][0], ahi[ks][1], ahi[ks][2],
                             ahi[ks][3], bh[ks][nt][0], bh[ks][nt][1]);
                    mma_bf16(d0, d1, d2, d3, ahi[ks][0], ahi[ks][1], ahi[ks][2],
                             ahi[ks][3], bl0, bl1);
                    mma_bf16(d0, d1, d2, d3, alo[ks][0], alo[ks][1], alo[ks][2],
                             alo[ks][3], bh[ks][nt][0], bh[ks][nt][1]);
                }
                const float g0 = tanh_pre(d0);
                const float g1 = tanh_pre(d1);
                const float g2 = tanh_pre(d2);
                const float g3 = tanh_pre(d3);
                const ulonglong2 w3v = *(const ulonglong2*)&tw3pk[nt][tid][0];
                accP_lo = fma2(dup2(g0), w3v.x, accP_lo);
                accP_lo = fma2(dup2(g1), w3v.y, accP_lo);
                accP_hi = fma2(dup2(g2), w3v.x, accP_hi);
                accP_hi = fma2(dup2(g3), w3v.y, accP_hi);
            }

            // ---- reduce over the 4 tig lanes of each element row ----
            accP_lo = add2(accP_lo, shfl_xor64(accP_lo, 1));
            accP_lo = add2(accP_lo, shfl_xor64(accP_lo, 2));
            accP_hi = add2(accP_hi, shfl_xor64(accP_hi, 1));
            accP_hi = add2(accP_hi, shfl_xor64(accP_hi, 2));
            if (tig == 0) {
                pbuf[w][gid] = accP_lo;
                pbuf[w][gid + 8] = accP_hi;
            }
            __syncthreads();   // partials ready; also WAR cover for afp

            const u64 k_lo = add2(add2(pbuf[0][gid], pbuf[1][gid]), b3p);
            const u64 k_hi = add2(add2(pbuf[0][gid + 8], pbuf[1][gid + 8]), b3p);
            ksm[w][st][gid] = k_lo;        // per-warp copy; self-coherent
            ksm[w][st][gid + 8] = k_hi;    // (4 tig lanes write same value)

            const float2 cbc = cB6[st];
            const u64 cb = *(const u64*)&cbc;
            comb_lo = fma2(cb, k_lo, comb_lo);
            comb_hi = fma2(cb, k_hi, comb_hi);
        }

        // ---- advance (running combine, no ksm re-reads) ----
        y_lo = fma2(dtp, comb_lo, y_lo);
        y_hi = fma2(dtp, comb_hi, y_hi);
        if (w == 0 && tig == 0) {
            o8[(size_t)(t + 1) * NB + e0 + gid] = y_lo;
            o8[(size_t)(t + 1) * NB + e0 + gid + 8] = y_hi;
        }
    }
}

extern "C" void kernel_launch(void* const* d_in, const int* in_sizes, int n_in,
                              void* d_out, int out_size) {
    const float* y0 = (const float*)d_in[0];
    const float* ts = (const float*)d_in[1];
    const float* W1 = (const float*)d_in[2];
    const float* b1 = (const float*)d_in[3];
    const float* W2 = (const float*)d_in[4];
    const float* b2 = (const float*)d_in[5];
    const float* W3 = (const float*)d_in[6];
    const float* b3 = (const float*)d_in[7];
    ode_kernel<<<GRID, TPB>>>(y0, ts, W1, b1, W2, b2, W3, b3, (float*)d_out);
}

// round 16
// speedup vs baseline: 3.7538x; 1.0129x over previous
#include <cuda_runtime.h>
#include <cstdint>

#define NB 16384
#define NT 1024
#define HH 64
#define TPB 64                 // warp-pair: 16 elements; j split 32/32
#define GRID (NB / 16)         // 1024 blocks (single wave at 7 blocks/SM)

#define L2E2 2.8853900817779268f   // 2*log2(e), folded into W1/b1/W2/b2

typedef unsigned long long u64;
typedef uint32_t u32;

static __device__ __forceinline__ u64 fma2(u64 a, u64 b, u64 c) {
    u64 d;
    asm("fma.rn.f32x2 %0, %1, %2, %3;" : "=l"(d) : "l"(a), "l"(b), "l"(c));
    return d;
}
static __device__ __forceinline__ u64 add2(u64 a, u64 b) {
    u64 d;
    asm("add.rn.f32x2 %0, %1, %2;" : "=l"(d) : "l"(a), "l"(b));
    return d;
}
static __device__ __forceinline__ u64 pk(float a, float b) {
    u64 d;
    asm("mov.b64 %0, {%1, %2};" : "=l"(d) : "f"(a), "f"(b));
    return d;
}
static __device__ __forceinline__ u64 dup2(float a) {
    u64 d;
    asm("mov.b64 %0, {%1, %1};" : "=l"(d) : "f"(a));
    return d;
}
static __device__ __forceinline__ void upk(u64 v, float& a, float& b) {
    asm("mov.b64 {%0, %1}, %2;" : "=f"(a), "=f"(b) : "l"(v));
}
static __device__ __forceinline__ u64 shfl_xor64(u64 v, int m) {
    u32 lo = (u32)v, hi = (u32)(v >> 32);
    lo = __shfl_xor_sync(0xffffffffu, lo, m);
    hi = __shfl_xor_sync(0xffffffffu, hi, m);
    return ((u64)hi << 32) | lo;
}
// tanh with prescaled arg a = 2*log2(e)*x: tanh(x) = 1 - 2/(2^a + 1).
static __device__ __forceinline__ float tanh_pre(float a) {
    float e, r;
    asm("ex2.approx.f32 %0, %1;" : "=f"(e) : "f"(a));
    asm("rcp.approx.f32 %0, %1;" : "=f"(r) : "f"(e + 1.0f));
    return fmaf(-2.0f, r, 1.0f);
}
// pack two f32 -> bf16x2; lo half = first arg (PTX: first source -> upper).
static __device__ __forceinline__ u32 bfpack(float lo, float hi) {
    u32 d;
    asm("cvt.rn.bf16x2.f32 %0, %1, %2;" : "=r"(d) : "f"(hi), "f"(lo));
    return d;
}
// m16n8k16 row.col bf16 MMA, fp32 accumulate (plain sm_80+ HMMA).
static __device__ __forceinline__ void mma_bf16(float& d0, float& d1, float& d2,
                                                float& d3, u32 a0, u32 a1,
                                                u32 a2, u32 a3, u32 b0, u32 b1) {
    asm("mma.sync.aligned.m16n8k16.row.col.f32.bf16.bf16.f32 "
        "{%0,%1,%2,%3}, {%4,%5,%6,%7}, {%8,%9}, {%0,%1,%2,%3};"
        : "+f"(d0), "+f"(d1), "+f"(d2), "+f"(d3)
        : "r"(a0), "r"(a1), "r"(a2), "r"(a3), "r"(b0), "r"(b1));
}

__device__ __constant__ float2 cA2[5][5] = {
    {{1.f/5, 1.f/5}, {0,0}, {0,0}, {0,0}, {0,0}},
    {{3.f/40, 3.f/40}, {9.f/40, 9.f/40}, {0,0}, {0,0}, {0,0}},
    {{44.f/45, 44.f/45}, {-56.f/15, -56.f/15}, {32.f/9, 32.f/9}, {0,0}, {0,0}},
    {{(float)(19372.0/6561.0), (float)(19372.0/6561.0)},
     {(float)(-25360.0/2187.0), (float)(-25360.0/2187.0)},
     {(float)(64448.0/6561.0), (float)(64448.0/6561.0)},
     {(float)(-212.0/729.0), (float)(-212.0/729.0)}, {0,0}},
    {{(float)(9017.0/3168.0), (float)(9017.0/3168.0)},
     {(float)(-355.0/33.0), (float)(-355.0/33.0)},
     {(float)(46732.0/5247.0), (float)(46732.0/5247.0)},
     {(float)(49.0/176.0), (float)(49.0/176.0)},
     {(float)(-5103.0/18656.0), (float)(-5103.0/18656.0)}},
};
// Per-stage output weights (b2 of Dopri5 is 0 at stage index 1).
__device__ __constant__ float2 cB6[6] = {
    {(float)(35.0/384.0), (float)(35.0/384.0)},
    {0.f, 0.f},
    {(float)(500.0/1113.0), (float)(500.0/1113.0)},
    {(float)(125.0/192.0), (float)(125.0/192.0)},
    {(float)(-2187.0/6784.0), (float)(-2187.0/6784.0)},
    {(float)(11.0/84.0), (float)(11.0/84.0)},
};

__global__ void __launch_bounds__(TPB, 7)
ode_kernel(const float* __restrict__ y0, const float* __restrict__ ts,
           const float* __restrict__ W1, const float* __restrict__ b1,
           const float* __restrict__ W2, const float* __restrict__ b2,
           const float* __restrict__ W3, const float* __restrict__ b3,
           float* __restrict__ out) {
    // B-lo fragments, WARP-RELATIVE ks order: slot i<2 = own warp's global
    // ks 2w+i, slot i>=2 = peer's. Matches bh[] so all MMA indices are static.
    __shared__ u32 tabblo[16][64][2];                  // (8 KB)
    __shared__ __align__(16) float tw1pk[8][64][4];    // (wx,wy,b,0) (8 KB)
    __shared__ __align__(16) u64 tw3pk[4][64][2];      // W3 pairs (4 KB)
    __shared__ u64 tb2[4][64];                          // b2 init pairs (2 KB)
    __shared__ __align__(16) u32 afp[2][2][2][32][4];   // [warp][ksl][hi/lo] (4 KB)
    __shared__ u64 pbuf[2][16];                         // layer-3 partials
    __shared__ u64 ksm[2][6][16];                       // per-warp RK k's

    const int tid = threadIdx.x;
    const int w = tid >> 5, lane = tid & 31;
    const int gid = lane >> 2, tig = lane & 3;
    const int pw = 1 - w;          // peer warp

    // ---- per-lane layer-1 table (unit set matches A-fragment cols) ----
#pragma unroll
    for (int q = 0; q < 8; q++) {
        const int ksl = q >> 2, idx = q & 3;
        const int ks = 2 * w + ksl;         // own warp's global k-steps
        const int u = 16 * ks + 2 * tig + (idx & 1) + 8 * (idx >> 1);
        tw1pk[q][tid][0] = W1[2 * u] * L2E2;
        tw1pk[q][tid][1] = W1[2 * u + 1] * L2E2;
        tw1pk[q][tid][2] = b1[u] * L2E2;
        tw1pk[q][tid][3] = 0.f;
    }
    // ---- per-lane W3 pairs: tw3pk[nt][tid][c] for j = 32w+8nt+2tig+c ----
#pragma unroll
    for (int q = 0; q < 8; q++) {
        const int j = 32 * w + 8 * (q >> 1) + 2 * tig + (q & 1);
        tw3pk[q >> 1][tid][q & 1] = pk(W3[j], W3[HH + j]);
    }
    // ---- per-lane b2 accumulator-init pairs ----
#pragma unroll
    for (int nt = 0; nt < 4; nt++) {
        const int j0 = 32 * w + 8 * nt + 2 * tig;
        tb2[nt][tid] = pk(b2[j0] * L2E2, b2[j0 + 1] * L2E2);
    }
    // ---- B fragments, warp-relative ks order: hi regs, lo residual smem ----
    u32 bh[4][4][2];   // [i local ks][nt][r]
#pragma unroll
    for (int i = 0; i < 4; i++) {
        const int gks = (i < 2) ? (2 * w + i) : (2 * pw + (i - 2));
#pragma unroll
        for (int nt = 0; nt < 4; nt++) {
            const int j = 32 * w + 8 * nt + gid;   // B col = n = j
#pragma unroll
            for (int r = 0; r < 2; r++) {
                const int k0 = 16 * gks + 2 * tig + 8 * r;  // B rows = k
                const float v0 = W2[j * HH + k0] * L2E2;
                const float v1 = W2[j * HH + k0 + 1] * L2E2;
                const u32 ph = bfpack(v0, v1);
                const float r0 = v0 - __uint_as_float(ph << 16);
                const float r1 = v1 - __uint_as_float(ph & 0xffff0000u);
                bh[i][nt][r] = ph;
                tabblo[i * 4 + nt][tid][r] = bfpack(r0, r1);
            }
        }
    }
    __syncthreads();

    const int e0 = blockIdx.x * 16;
    u64 y_lo = ((const u64*)y0)[e0 + gid];       // element gid
    u64 y_hi = ((const u64*)y0)[e0 + gid + 8];   // element gid+8
    u64* o8 = (u64*)out;
    if (w == 0 && tig == 0) {   // SaveAt includes the initial state
        o8[e0 + gid] = y_lo;
        o8[e0 + gid + 8] = y_hi;
    }
    const u64 b3p = pk(b3[0], b3[1]);

    for (int t = 0; t < NT - 1; t++) {
        const float dtv = ts[t + 1] - ts[t];     // L1/L2-cached LDG
        const u64 dtp = dup2(dtv);
        u64 comb_lo = 0ull, comb_hi = 0ull;      // running B-combine

#pragma unroll 1
        for (int st = 0; st < 6; st++) {
            // ---- stage input (both elements; per-warp ksm copy) ----
            u64 s_lo, s_hi;
            if (st == 0) {
                s_lo = y_lo; s_hi = y_hi;
            } else {
                u64 al = 0ull, ah = 0ull;
                for (int i = 0; i < st; i++) {
                    const float2 cc = cA2[st - 1][i];
                    const u64 c = *(const u64*)&cc;
                    al = fma2(c, ksm[w][i][gid], al);
                    ah = fma2(c, ksm[w][i][gid + 8], ah);
                }
                s_lo = fma2(dtp, al, y_lo);
                s_hi = fma2(dtp, ah, y_hi);
            }
            float sxl, syl, sxh, syh;
            upk(s_lo, sxl, syl);
            upk(s_hi, sxh, syh);

            // ---- layer 1 (own 2 k-steps) -> A frags: regs + peer copy ----
            u32 ah_all[4][4], al_all[4][4];   // [local ks][frag], 0/1 = own
#pragma unroll
            for (int ksl = 0; ksl < 2; ksl++) {
                float hl[4], hh[4];
#pragma unroll
                for (int idx = 0; idx < 4; idx++) {
                    const float4 wv = *(const float4*)&tw1pk[4 * ksl + idx][tid][0];
                    hl[idx] = tanh_pre(fmaf(sxl, wv.x, fmaf(syl, wv.y, wv.z)));
                    hh[idx] = tanh_pre(fmaf(sxh, wv.x, fmaf(syh, wv.y, wv.z)));
                }
                // hi fragments (a0: row gid; a1: row gid+8; a2/a3: cols +8)
                const u32 p0 = bfpack(hl[0], hl[1]);
                const u32 p1 = bfpack(hh[0], hh[1]);
                const u32 p2 = bfpack(hl[2], hl[3]);
                const u32 p3 = bfpack(hh[2], hh[3]);
                // lo residuals (bf16 -> f32 is a 16-bit shift)
                const u32 q0 = bfpack(hl[0] - __uint_as_float(p0 << 16),
                                      hl[1] - __uint_as_float(p0 & 0xffff0000u));
                const u32 q1 = bfpack(hh[0] - __uint_as_float(p1 << 16),
                                      hh[1] - __uint_as_float(p1 & 0xffff0000u));
                const u32 q2 = bfpack(hl[2] - __uint_as_float(p2 << 16),
                                      hl[3] - __uint_as_float(p2 & 0xffff0000u));
                const u32 q3 = bfpack(hh[2] - __uint_as_float(p3 << 16),
                                      hh[3] - __uint_as_float(p3 & 0xffff0000u));
                ah_all[ksl][0] = p0; ah_all[ksl][1] = p1;
                ah_all[ksl][2] = p2; ah_all[ksl][3] = p3;
                al_all[ksl][0] = q0; al_all[ksl][1] = q1;
                al_all[ksl][2] = q2; al_all[ksl][3] = q3;
                // publish for the peer warp only
                *(uint4*)&afp[w][ksl][0][lane][0] = make_uint4(p0, p1, p2, p3);
                *(uint4*)&afp[w][ksl][1][lane][0] = make_uint4(q0, q1, q2, q3);
            }
            __syncthreads();   // peer's A frags available

            // ---- load peer's 2 k-steps into local slots 2,3 ----
#pragma unroll
            for (int ksl = 0; ksl < 2; ksl++) {
                const uint4 hv = *(const uint4*)&afp[pw][ksl][0][lane][0];
                const uint4 lv = *(const uint4*)&afp[pw][ksl][1][lane][0];
                ah_all[2 + ksl][0] = hv.x; ah_all[2 + ksl][1] = hv.y;
                ah_all[2 + ksl][2] = hv.z; ah_all[2 + ksl][3] = hv.w;
                al_all[2 + ksl][0] = lv.x; al_all[2 + ksl][1] = lv.y;
                al_all[2 + ksl][2] = lv.z; al_all[2 + ksl][3] = lv.w;
            }

            // ---- layer 2 MMAs + fused epilogue (this warp's 32 j) ----
            u64 accP_lo = 0ull, accP_hi = 0ull;
#pragma unroll
            for (int nt = 0; nt < 4; nt++) {
                float d0, d1, d2, d3;
                {
                    float blo, bhi2;
                    upk(tb2[nt][tid], blo, bhi2);
                    d0 = blo; d1 = bhi2; d2 = blo; d3 = bhi2;
                }
#pragma unroll
                for (int i = 0; i < 4; i++) {   // local ks (own first)
                    const u64 blp = *(const u64*)&tabblo[i * 4 + nt][tid][0];
                    const u32 bl0 = (u32)blp, bl1 = (u32)(blp >> 32);
                    mma_bf16(d0, d1, d2, d3, ah_all[i][0], ah_all[i][1],
                             ah_all[i][2], ah_all[i][3], bh[i][nt][0],
                             bh[i][nt][1]);
                    mma_bf16(d0, d1, d2, d3, ah_all[i][0], ah_all[i][1],
                             ah_all[i][2], ah_all[i][3], bl0, bl1);
                    mma_bf16(d0, d1, d2, d3, al_all[i][0], al_all[i][1],
                             al_all[i][2], al_all[i][3], bh[i][nt][0],
                             bh[i][nt][1]);
                }
                const float g0 = tanh_pre(d0);
                const float g1 = tanh_pre(d1);
                const float g2 = tanh_pre(d2);
                const float g3 = tanh_pre(d3);
                const ulonglong2 w3v = *(const ulonglong2*)&tw3pk[nt][tid][0];
                accP_lo = fma2(dup2(g0), w3v.x, accP_lo);
                accP_lo = fma2(dup2(g1), w3v.y, accP_lo);
                accP_hi = fma2(dup2(g2), w3v.x, accP_hi);
                accP_hi = fma2(dup2(g3), w3v.y, accP_hi);
            }

            // ---- reduce over the 4 tig lanes of each element row ----
            accP_lo = add2(accP_lo, shfl_xor64(accP_lo, 1));
            accP_lo = add2(accP_lo, shfl_xor64(accP_lo, 2));
            accP_hi = add2(accP_hi, shfl_xor64(accP_hi, 1));
            accP_hi = add2(accP_hi, shfl_xor64(accP_hi, 2));
            if (tig == 0) {
                pbuf[w][gid] = accP_lo;
                pbuf[w][gid + 8] = accP_hi;
            }
            __syncthreads();   // partials ready; also WAR cover for afp

            const u64 k_lo = add2(add2(pbuf[0][gid], pbuf[1][gid]), b3p);
            const u64 k_hi = add2(add2(pbuf[0][gid + 8], pbuf[1][gid + 8]), b3p);
            ksm[w][st][gid] = k_lo;        // per-warp copy; self-coherent
            ksm[w][st][gid + 8] = k_hi;    // (4 tig lanes write same value)

            const float2 cbc = cB6[st];
            const u64 cb = *(const u64*)&cbc;
            comb_lo = fma2(cb, k_lo, comb_lo);
            comb_hi = fma2(cb, k_hi, comb_hi);
        }

        // ---- advance (running combine, no ksm re-reads) ----
        y_lo = fma2(dtp, comb_lo, y_lo);
        y_hi = fma2(dtp, comb_hi, y_hi);
        if (w == 0 && tig == 0) {
            o8[(size_t)(t + 1) * NB + e0 + gid] = y_lo;
            o8[(size_t)(t + 1) * NB + e0 + gid + 8] = y_hi;
        }
    }
}

extern "C" void kernel_launch(void* const* d_in, const int* in_sizes, int n_in,
                              void* d_out, int out_size) {
    const float* y0 = (const float*)d_in[0];
    const float* ts = (const float*)d_in[1];
    const float* W1 = (const float*)d_in[2];
    const float* b1 = (const float*)d_in[3];
    const float* W2 = (const float*)d_in[4];
    const float* b2 = (const float*)d_in[5];
    const float* W3 = (const float*)d_in[6];
    const float* b3 = (const float*)d_in[7];
    ode_kernel<<<GRID, TPB>>>(y0, ts, W1, b1, W2, b2, W3, b3, (float*)d_out);
}

// round 17
// speedup vs baseline: 5.6157x; 1.4960x over previous
#include <cuda_runtime.h>
#include <cstdint>

#define NB 16384
#define NT 1024
#define HH 64
#define TPB 64                 // warp-pair: 16 elements; j split 32/32
#define GRID (NB / 16)         // 1024 blocks (single wave at 7 blocks/SM)

typedef unsigned long long u64;
typedef uint32_t u32;

static __device__ __forceinline__ u64 fma2(u64 a, u64 b, u64 c) {
    u64 d;
    asm("fma.rn.f32x2 %0, %1, %2, %3;" : "=l"(d) : "l"(a), "l"(b), "l"(c));
    return d;
}
static __device__ __forceinline__ u64 add2(u64 a, u64 b) {
    u64 d;
    asm("add.rn.f32x2 %0, %1, %2;" : "=l"(d) : "l"(a), "l"(b));
    return d;
}
static __device__ __forceinline__ u64 pk(float a, float b) {
    u64 d;
    asm("mov.b64 %0, {%1, %2};" : "=l"(d) : "f"(a), "f"(b));
    return d;
}
static __device__ __forceinline__ u64 dup2(float a) {
    u64 d;
    asm("mov.b64 %0, {%1, %1};" : "=l"(d) : "f"(a));
    return d;
}
static __device__ __forceinline__ void upk(u64 v, float& a, float& b) {
    asm("mov.b64 {%0, %1}, %2;" : "=f"(a), "=f"(b) : "l"(v));
}
static __device__ __forceinline__ u64 shfl_xor64(u64 v, int m) {
    u32 lo = (u32)v, hi = (u32)(v >> 32);
    lo = __shfl_xor_sync(0xffffffffu, lo, m);
    hi = __shfl_xor_sync(0xffffffffu, hi, m);
    return ((u64)hi << 32) | lo;
}
// HW tanh (sm_75+): 1 MUFU op, max rel err ~2^-11. Error contraction measured
// at ~1.2x through 1023 steps -> final ~1-3e-4, inside the 1e-3 gate.
static __device__ __forceinline__ float tanh_hw(float x) {
    float r;
    asm("tanh.approx.f32 %0, %1;" : "=f"(r) : "f"(x));
    return r;
}
// pack two f32 -> bf16x2; lo half = first arg (PTX: first source -> upper).
static __device__ __forceinline__ u32 bfpack(float lo, float hi) {
    u32 d;
    asm("cvt.rn.bf16x2.f32 %0, %1, %2;" : "=r"(d) : "f"(hi), "f"(lo));
    return d;
}
// m16n8k16 row.col bf16 MMA, fp32 accumulate (plain sm_80+ HMMA).
static __device__ __forceinline__ void mma_bf16(float& d0, float& d1, float& d2,
                                                float& d3, u32 a0, u32 a1,
                                                u32 a2, u32 a3, u32 b0, u32 b1) {
    asm("mma.sync.aligned.m16n8k16.row.col.f32.bf16.bf16.f32 "
        "{%0,%1,%2,%3}, {%4,%5,%6,%7}, {%8,%9}, {%0,%1,%2,%3};"
        : "+f"(d0), "+f"(d1), "+f"(d2), "+f"(d3)
        : "r"(a0), "r"(a1), "r"(a2), "r"(a3), "r"(b0), "r"(b1));
}

__device__ __constant__ float2 cA2[5][5] = {
    {{1.f/5, 1.f/5}, {0,0}, {0,0}, {0,0}, {0,0}},
    {{3.f/40, 3.f/40}, {9.f/40, 9.f/40}, {0,0}, {0,0}, {0,0}},
    {{44.f/45, 44.f/45}, {-56.f/15, -56.f/15}, {32.f/9, 32.f/9}, {0,0}, {0,0}},
    {{(float)(19372.0/6561.0), (float)(19372.0/6561.0)},
     {(float)(-25360.0/2187.0), (float)(-25360.0/2187.0)},
     {(float)(64448.0/6561.0), (float)(64448.0/6561.0)},
     {(float)(-212.0/729.0), (float)(-212.0/729.0)}, {0,0}},
    {{(float)(9017.0/3168.0), (float)(9017.0/3168.0)},
     {(float)(-355.0/33.0), (float)(-355.0/33.0)},
     {(float)(46732.0/5247.0), (float)(46732.0/5247.0)},
     {(float)(49.0/176.0), (float)(49.0/176.0)},
     {(float)(-5103.0/18656.0), (float)(-5103.0/18656.0)}},
};
// Per-stage output weights (b2 of Dopri5 is 0 at stage index 1).
__device__ __constant__ float2 cB6[6] = {
    {(float)(35.0/384.0), (float)(35.0/384.0)},
    {0.f, 0.f},
    {(float)(500.0/1113.0), (float)(500.0/1113.0)},
    {(float)(125.0/192.0), (float)(125.0/192.0)},
    {(float)(-2187.0/6784.0), (float)(-2187.0/6784.0)},
    {(float)(11.0/84.0), (float)(11.0/84.0)},
};

__global__ void __launch_bounds__(TPB, 7)
ode_kernel(const float* __restrict__ y0, const float* __restrict__ ts,
           const float* __restrict__ W1, const float* __restrict__ b1,
           const float* __restrict__ W2, const float* __restrict__ b2,
           const float* __restrict__ W3, const float* __restrict__ b3,
           float* __restrict__ out) {
    // B-lo fragments, WARP-RELATIVE ks order: slot i<2 = own warp's global
    // ks 2w+i, slot i>=2 = peer's. Matches bh[] so all MMA indices are static.
    __shared__ u32 tabblo[16][64][2];                  // (8 KB)
    __shared__ __align__(16) float tw1pk[8][64][4];    // (wx,wy,b,0) (8 KB)
    __shared__ __align__(16) u64 tw3pk[4][64][2];      // W3 pairs (4 KB)
    __shared__ u64 tb2[4][64];                          // b2 init pairs (2 KB)
    __shared__ __align__(16) u32 afp[2][2][2][32][4];   // [warp][ksl][hi/lo] (4 KB)
    __shared__ u64 pbuf[2][16];                         // layer-3 partials
    __shared__ u64 ksm[2][6][16];                       // per-warp RK k's

    const int tid = threadIdx.x;
    const int w = tid >> 5, lane = tid & 31;
    const int gid = lane >> 2, tig = lane & 3;
    const int pw = 1 - w;          // peer warp

    // ---- per-lane layer-1 table (unit set matches A-fragment cols) ----
#pragma unroll
    for (int q = 0; q < 8; q++) {
        const int ksl = q >> 2, idx = q & 3;
        const int ks = 2 * w + ksl;         // own warp's global k-steps
        const int u = 16 * ks + 2 * tig + (idx & 1) + 8 * (idx >> 1);
        tw1pk[q][tid][0] = W1[2 * u];
        tw1pk[q][tid][1] = W1[2 * u + 1];
        tw1pk[q][tid][2] = b1[u];
        tw1pk[q][tid][3] = 0.f;
    }
    // ---- per-lane W3 pairs: tw3pk[nt][tid][c] for j = 32w+8nt+2tig+c ----
#pragma unroll
    for (int q = 0; q < 8; q++) {
        const int j = 32 * w + 8 * (q >> 1) + 2 * tig + (q & 1);
        tw3pk[q >> 1][tid][q & 1] = pk(W3[j], W3[HH + j]);
    }
    // ---- per-lane b2 accumulator-init pairs ----
#pragma unroll
    for (int nt = 0; nt < 4; nt++) {
        const int j0 = 32 * w + 8 * nt + 2 * tig;
        tb2[nt][tid] = pk(b2[j0], b2[j0 + 1]);
    }
    // ---- B fragments, warp-relative ks order: hi regs, lo residual smem ----
    u32 bh[4][4][2];   // [i local ks][nt][r]
#pragma unroll
    for (int i = 0; i < 4; i++) {
        const int gks = (i < 2) ? (2 * w + i) : (2 * pw + (i - 2));
#pragma unroll
        for (int nt = 0; nt < 4; nt++) {
            const int j = 32 * w + 8 * nt + gid;   // B col = n = j
#pragma unroll
            for (int r = 0; r < 2; r++) {
                const int k0 = 16 * gks + 2 * tig + 8 * r;  // B rows = k
                const float v0 = W2[j * HH + k0];
                const float v1 = W2[j * HH + k0 + 1];
                const u32 ph = bfpack(v0, v1);
                const float r0 = v0 - __uint_as_float(ph << 16);
                const float r1 = v1 - __uint_as_float(ph & 0xffff0000u);
                bh[i][nt][r] = ph;
                tabblo[i * 4 + nt][tid][r] = bfpack(r0, r1);
            }
        }
    }
    __syncthreads();

    const int e0 = blockIdx.x * 16;
    u64 y_lo = ((const u64*)y0)[e0 + gid];       // element gid
    u64 y_hi = ((const u64*)y0)[e0 + gid + 8];   // element gid+8
    u64* o8 = (u64*)out;
    if (w == 0 && tig == 0) {   // SaveAt includes the initial state
        o8[e0 + gid] = y_lo;
        o8[e0 + gid + 8] = y_hi;
    }
    const u64 b3p = pk(b3[0], b3[1]);

    for (int t = 0; t < NT - 1; t++) {
        const float dtv = ts[t + 1] - ts[t];     // L1/L2-cached LDG
        const u64 dtp = dup2(dtv);
        u64 comb_lo = 0ull, comb_hi = 0ull;      // running B-combine

#pragma unroll 1
        for (int st = 0; st < 6; st++) {
            // ---- stage input (both elements; per-warp ksm copy) ----
            u64 s_lo, s_hi;
            if (st == 0) {
                s_lo = y_lo; s_hi = y_hi;
            } else {
                u64 al = 0ull, ah = 0ull;
                for (int i = 0; i < st; i++) {
                    const float2 cc = cA2[st - 1][i];
                    const u64 c = *(const u64*)&cc;
                    al = fma2(c, ksm[w][i][gid], al);
                    ah = fma2(c, ksm[w][i][gid + 8], ah);
                }
                s_lo = fma2(dtp, al, y_lo);
                s_hi = fma2(dtp, ah, y_hi);
            }
            float sxl, syl, sxh, syh;
            upk(s_lo, sxl, syl);
            upk(s_hi, sxh, syh);

            // ---- layer 1 (own 2 k-steps) -> A frags: regs + peer copy ----
            u32 ah_all[4][4], al_all[4][4];   // [local ks][frag], 0/1 = own
#pragma unroll
            for (int ksl = 0; ksl < 2; ksl++) {
                float hl[4], hh[4];
#pragma unroll
                for (int idx = 0; idx < 4; idx++) {
                    const float4 wv = *(const float4*)&tw1pk[4 * ksl + idx][tid][0];
                    hl[idx] = tanh_hw(fmaf(sxl, wv.x, fmaf(syl, wv.y, wv.z)));
                    hh[idx] = tanh_hw(fmaf(sxh, wv.x, fmaf(syh, wv.y, wv.z)));
                }
                // hi fragments (a0: row gid; a1: row gid+8; a2/a3: cols +8)
                const u32 p0 = bfpack(hl[0], hl[1]);
                const u32 p1 = bfpack(hh[0], hh[1]);
                const u32 p2 = bfpack(hl[2], hl[3]);
                const u32 p3 = bfpack(hh[2], hh[3]);
                // lo residuals (bf16 -> f32 is a 16-bit shift)
                const u32 q0 = bfpack(hl[0] - __uint_as_float(p0 << 16),
                                      hl[1] - __uint_as_float(p0 & 0xffff0000u));
                const u32 q1 = bfpack(hh[0] - __uint_as_float(p1 << 16),
                                      hh[1] - __uint_as_float(p1 & 0xffff0000u));
                const u32 q2 = bfpack(hl[2] - __uint_as_float(p2 << 16),
                                      hl[3] - __uint_as_float(p2 & 0xffff0000u));
                const u32 q3 = bfpack(hh[2] - __uint_as_float(p3 << 16),
                                      hh[3] - __uint_as_float(p3 & 0xffff0000u));
                ah_all[ksl][0] = p0; ah_all[ksl][1] = p1;
                ah_all[ksl][2] = p2; ah_all[ksl][3] = p3;
                al_all[ksl][0] = q0; al_all[ksl][1] = q1;
                al_all[ksl][2] = q2; al_all[ksl][3] = q3;
                // publish for the peer warp only
                *(uint4*)&afp[w][ksl][0][lane][0] = make_uint4(p0, p1, p2, p3);
                *(uint4*)&afp[w][ksl][1][lane][0] = make_uint4(q0, q1, q2, q3);
            }
            __syncthreads();   // peer's A frags available

            // ---- load peer's 2 k-steps into local slots 2,3 ----
#pragma unroll
            for (int ksl = 0; ksl < 2; ksl++) {
                const uint4 hv = *(const uint4*)&afp[pw][ksl][0][lane][0];
                const uint4 lv = *(const uint4*)&afp[pw][ksl][1][lane][0];
                ah_all[2 + ksl][0] = hv.x; ah_all[2 + ksl][1] = hv.y;
                ah_all[2 + ksl][2] = hv.z; ah_all[2 + ksl][3] = hv.w;
                al_all[2 + ksl][0] = lv.x; al_all[2 + ksl][1] = lv.y;
                al_all[2 + ksl][2] = lv.z; al_all[2 + ksl][3] = lv.w;
            }

            // ---- layer 2 MMAs + fused epilogue (this warp's 32 j) ----
            u64 accP_lo = 0ull, accP_hi = 0ull;
#pragma unroll
            for (int nt = 0; nt < 4; nt++) {
                float d0, d1, d2, d3;
                {
                    float blo, bhi2;
                    upk(tb2[nt][tid], blo, bhi2);
                    d0 = blo; d1 = bhi2; d2 = blo; d3 = bhi2;
                }
#pragma unroll
                for (int i = 0; i < 4; i++) {   // local ks (own first)
                    const u64 blp = *(const u64*)&tabblo[i * 4 + nt][tid][0];
                    const u32 bl0 = (u32)blp, bl1 = (u32)(blp >> 32);
                    mma_bf16(d0, d1, d2, d3, ah_all[i][0], ah_all[i][1],
                             ah_all[i][2], ah_all[i][3], bh[i][nt][0],
                             bh[i][nt][1]);
                    mma_bf16(d0, d1, d2, d3, ah_all[i][0], ah_all[i][1],
                             ah_all[i][2], ah_all[i][3], bl0, bl1);
                    mma_bf16(d0, d1, d2, d3, al_all[i][0], al_all[i][1],
                             al_all[i][2], al_all[i][3], bh[i][nt][0],
                             bh[i][nt][1]);
                }
                const float g0 = tanh_hw(d0);
                const float g1 = tanh_hw(d1);
                const float g2 = tanh_hw(d2);
                const float g3 = tanh_hw(d3);
                const ulonglong2 w3v = *(const ulonglong2*)&tw3pk[nt][tid][0];
                accP_lo = fma2(dup2(g0), w3v.x, accP_lo);
                accP_lo = fma2(dup2(g1), w3v.y, accP_lo);
                accP_hi = fma2(dup2(g2), w3v.x, accP_hi);
                accP_hi = fma2(dup2(g3), w3v.y, accP_hi);
            }

            // ---- reduce over the 4 tig lanes of each element row ----
            accP_lo = add2(accP_lo, shfl_xor64(accP_lo, 1));
            accP_lo = add2(accP_lo, shfl_xor64(accP_lo, 2));
            accP_hi = add2(accP_hi, shfl_xor64(accP_hi, 1));
            accP_hi = add2(accP_hi, shfl_xor64(accP_hi, 2));
            if (tig == 0) {
                pbuf[w][gid] = accP_lo;
                pbuf[w][gid + 8] = accP_hi;
            }
            __syncthreads();   // partials ready; also WAR cover for afp

            const u64 k_lo = add2(add2(pbuf[0][gid], pbuf[1][gid]), b3p);
            const u64 k_hi = add2(add2(pbuf[0][gid + 8], pbuf[1][gid + 8]), b3p);
            ksm[w][st][gid] = k_lo;        // per-warp copy; self-coherent
            ksm[w][st][gid + 8] = k_hi;    // (4 tig lanes write same value)

            const float2 cbc = cB6[st];
            const u64 cb = *(const u64*)&cbc;
            comb_lo = fma2(cb, k_lo, comb_lo);
            comb_hi = fma2(cb, k_hi, comb_hi);
        }

        // ---- advance (running combine, no ksm re-reads) ----
        y_lo = fma2(dtp, comb_lo, y_lo);
        y_hi = fma2(dtp, comb_hi, y_hi);
        if (w == 0 && tig == 0) {
            o8[(size_t)(t + 1) * NB + e0 + gid] = y_lo;
            o8[(size_t)(t + 1) * NB + e0 + gid + 8] = y_hi;
        }
    }
}

extern "C" void kernel_launch(void* const* d_in, const int* in_sizes, int n_in,
                              void* d_out, int out_size) {
    const float* y0 = (const float*)d_in[0];
    const float* ts = (const float*)d_in[1];
    const float* W1 = (const float*)d_in[2];
    const float* b1 = (const float*)d_in[3];
    const float* W2 = (const float*)d_in[4];
    const float* b2 = (const float*)d_in[5];
    const float* W3 = (const float*)d_in[6];
    const float* b3 = (const float*)d_in[7];
    ode_kernel<<<GRID, TPB>>>(y0, ts, W1, b1, W2, b2, W3, b3, (float*)d_out);
}